// round 1
// baseline (speedup 1.0000x reference)
#include <cuda_runtime.h>
#include <math.h>

#define BS  512
#define LNUM 68
#define IMG 224
#define RS  7
#define R2  49
#define NLM (BS * LNUM)
#define LL  (LNUM * LNUM)

// ---------------- device scratch (no allocations allowed) ----------------
__device__ float  g_median[NLM];   // raw (unscaled) region medians
__device__ float  g_meds[NLM];     // scaled medians (*500)
__device__ float  g_maskf[NLM];    // per-landmark mask as float 0/1
__device__ double g_sumL;          // sum of masked loss elements
__device__ double g_sumM;          // sum of mask products

// ---------------- K1: per-landmark region median --------------------------
__global__ void k1_region_median(const float* __restrict__ depth,
                                 const float* __restrict__ lm,
                                 const float* __restrict__ sf,
                                 const float* __restrict__ bbox)
{
    int idx = blockIdx.x * blockDim.x + threadIdx.x;
    if (idx >= NLM) return;
    int b = idx / LNUM;

    float lmx = lm[idx * 2 + 0];
    float lmy = lm[idx * 2 + 1];
    // face_lm = (landmarks - bbox[:, :2]) * scale / img * 2 - 1  (same op order)
    float fx = (lmx - bbox[b * 4 + 0]) * sf[b * 2 + 0] / 224.0f * 2.0f - 1.0f;
    float fy = (lmy - bbox[b * 4 + 1]) * sf[b * 2 + 1] / 224.0f * 2.0f - 1.0f;

    // x = linspace(-3.5, 3.5, 7) / img * 2   (linspace: start + k*step, endpoint forced)
    float xs[RS];
#pragma unroll
    for (int k = 0; k < RS; k++) {
        float x = -3.5f + (float)k * (7.0f / 6.0f);
        if (k == RS - 1) x = 3.5f;
        xs[k] = x / 224.0f * 2.0f;
    }

    const float* dptr = depth + (size_t)b * IMG * IMG;
    float vals[R2];
#pragma unroll
    for (int p = 0; p < RS; p++) {
        // offsets[p][q] = (x[q], x[p]) : gy uses x[p], gx uses x[q]
        float gy = fy + xs[p];
        float iy = ((gy + 1.0f) * 224.0f - 1.0f) * 0.5f;
        int   yi = (int)rintf(iy);                   // round-half-even == jnp.round
        bool  vy = (yi >= 0) && (yi < IMG);
        int   yc = min(max(yi, 0), IMG - 1);
#pragma unroll
        for (int q = 0; q < RS; q++) {
            float gx = fx + xs[q];
            float ix = ((gx + 1.0f) * 224.0f - 1.0f) * 0.5f;
            int   xi = (int)rintf(ix);
            bool  v  = vy && (xi >= 0) && (xi < IMG);
            int   xc = min(max(xi, 0), IMG - 1);
            float val = dptr[yc * IMG + xc];
            vals[p * RS + q] = v ? val : 0.0f;
        }
    }

    // insertion sort (ascending)
    for (int i = 1; i < R2; i++) {
        float key = vals[i];
        int j = i - 1;
        while (j >= 0 && vals[j] > key) { vals[j + 1] = vals[j]; j--; }
        vals[j + 1] = key;
    }

    // st = clamp(count(s <= THR), 1, 48); med_ind = (st + 48) / 2
    int k = 0;
#pragma unroll
    for (int i = 0; i < R2; i++) k += (vals[i] <= 1e-4f) ? 1 : 0;
    int st = min(max(k, 1), R2 - 1);
    int mi = (st + R2 - 1) >> 1;
    g_median[idx] = vals[mi];
}

// ---------------- K2: per-batch lower median-of-medians + mask ------------
__global__ void k2_med_of_med()
{
    __shared__ float sm[LNUM];
    __shared__ float s_mom;
    int b = blockIdx.x;
    int t = threadIdx.x;

    if (b == 0 && t == 0) { g_sumL = 0.0; g_sumM = 0.0; }

    if (t < LNUM) sm[t] = g_median[b * LNUM + t];
    __syncthreads();

    if (t < LNUM) {
        float v = sm[t];
        int r = 0;
#pragma unroll 4
        for (int j = 0; j < LNUM; j++) {
            float w = sm[j];
            r += ((w < v) || (w == v && j < t)) ? 1 : 0;   // stable rank
        }
        if (r == (LNUM - 1) / 2) s_mom = v;                 // rank 33 = lower median
    }
    __syncthreads();

    if (t < LNUM) {
        float v = sm[t];
        float mask = (fabsf(v - s_mom) < (90.0f / 500.0f)) ? 1.0f : 0.0f;
        g_maskf[b * LNUM + t] = mask;
        g_meds[b * LNUM + t]  = v * 500.0f;
    }
}

// ---------------- K3: pairwise diff/mask/loss + reduction -----------------
__global__ void k3_pairwise(const float* __restrict__ rel,
                            float* __restrict__ out_diff,
                            float* __restrict__ out_mask)
{
    __shared__ float smed[LNUM];
    __shared__ float smask[LNUM];
    __shared__ double redL[8], redM[8];

    int b = blockIdx.x;
    for (int t = threadIdx.x; t < LNUM; t += blockDim.x) {
        smed[t]  = g_meds[b * LNUM + t];
        smask[t] = g_maskf[b * LNUM + t];
    }
    __syncthreads();

    double accL = 0.0, accM = 0.0;
    const size_t base = (size_t)b * LL;
    for (int t = threadIdx.x; t < LL; t += blockDim.x) {
        int i = t / LNUM;
        int j = t - i * LNUM;
        float diff = smed[i] - smed[j];
        float mk   = smask[i] * smask[j];
        float d    = rel[base + t] - diff;
        float ad   = fabsf(d);
        float le   = (ad < 1.0f) ? 0.5f * d * d : ad - 0.5f;
        if (out_diff) out_diff[base + t] = diff;
        if (out_mask) out_mask[base + t] = mk;
        accL += (double)(le * mk);
        accM += (double)mk;
    }

    // warp reduce
    unsigned m = 0xFFFFFFFFu;
#pragma unroll
    for (int o = 16; o > 0; o >>= 1) {
        accL += __shfl_down_sync(m, accL, o);
        accM += __shfl_down_sync(m, accM, o);
    }
    int wid = threadIdx.x >> 5;
    int lid = threadIdx.x & 31;
    if (lid == 0) { redL[wid] = accL; redM[wid] = accM; }
    __syncthreads();
    if (wid == 0) {
        int nw = blockDim.x >> 5;
        double vL = (lid < nw) ? redL[lid] : 0.0;
        double vM = (lid < nw) ? redM[lid] : 0.0;
#pragma unroll
        for (int o = 4; o > 0; o >>= 1) {
            vL += __shfl_down_sync(m, vL, o);
            vM += __shfl_down_sync(m, vM, o);
        }
        if (lid == 0) {
            atomicAdd(&g_sumL, vL);
            atomicAdd(&g_sumM, vM);
        }
    }
}

// ---------------- K4: final scalar ----------------------------------------
__global__ void k4_final(float* __restrict__ out_loss)
{
    out_loss[0] = (float)(g_sumL / (g_sumM + 1e-4));
}

extern "C" void kernel_launch(void* const* d_in, const int* in_sizes, int n_in,
                              void* d_out, int out_size)
{
    const float* rel   = (const float*)d_in[0];   // [BS, L, L]
    const float* depth = (const float*)d_in[1];   // [BS, 1, IMG, IMG]
    const float* lm    = (const float*)d_in[2];   // [BS, L, 2]
    const float* sf    = (const float*)d_in[3];   // [BS, 2]
    const float* bbox  = (const float*)d_in[4];   // [BS, 4]
    float* out = (float*)d_out;

    // flattened tuple layout: [loss(1)] [median_diff(BS*L*L)] [median_rel_mask(BS*L*L)]
    bool full = out_size >= 1 + 2 * BS * LL;
    float* out_diff = full ? (out + 1) : nullptr;
    float* out_mask = full ? (out + 1 + (size_t)BS * LL) : nullptr;

    k1_region_median<<<(NLM + 255) / 256, 256>>>(depth, lm, sf, bbox);
    k2_med_of_med<<<BS, 96>>>();
    k3_pairwise<<<BS, 256>>>(rel, out_diff, out_mask);
    k4_final<<<1, 1>>>(out);
}

// round 2
// speedup vs baseline: 3.1718x; 3.1718x over previous
#include <cuda_runtime.h>
#include <math.h>

#define BS    512
#define LNUM  68
#define IMG   224
#define RS    7
#define R2    49
#define LL    (LNUM * LNUM)
#define NTHR  544            // 17 warps, 4 landmarks per warp
#define FULLM 0xFFFFFFFFu
#define MB    0x1FFFFu       // lanes 0..16 hold slots 32..48

__device__ double   g_sumL = 0.0;
__device__ double   g_sumM = 0.0;
__device__ unsigned g_done = 0u;

// Sample one region slot s (0..48) for a landmark; exact replica of the
// reference's grid_sample-nearest arithmetic (rintf == jnp.round, half-even).
__device__ __forceinline__ float region_val(const float* __restrict__ dimg,
                                            float fx, float fy, int s)
{
    int p = s / RS, q = s - p * RS;
    float xp = (p == RS - 1) ? 3.5f : (-3.5f + (float)p * (7.0f / 6.0f));
    float xq = (q == RS - 1) ? 3.5f : (-3.5f + (float)q * (7.0f / 6.0f));
    xp = xp / 224.0f * 2.0f;
    xq = xq / 224.0f * 2.0f;
    float gy = fy + xp;                       // offsets[p][q] = (x[q], x[p])
    float gx = fx + xq;
    float iy = ((gy + 1.0f) * 224.0f - 1.0f) * 0.5f;
    float ix = ((gx + 1.0f) * 224.0f - 1.0f) * 0.5f;
    int yi = (int)rintf(iy);
    int xi = (int)rintf(ix);
    bool v = (yi >= 0) & (yi < IMG) & (xi >= 0) & (xi < IMG);
    int yc = min(max(yi, 0), IMG - 1);
    int xc = min(max(xi, 0), IMG - 1);
    float val = __ldg(dimg + yc * IMG + xc);
    return v ? val : 0.0f;
}

// Warp-cooperative order statistic of the 49 region values.
// v0 = slot(lane), v1 = slot(lane+32) (lanes 0..16; else +INF).
// Returns s[mi] where mi = (clamp(count(v<=THR),1,48)+48)/2 — exactly the
// reference's sorted-region median with the transition-index rule.
__device__ __forceinline__ float warp_region_median(float v0, float v1)
{
    unsigned le0 = __ballot_sync(FULLM, v0 <= 1e-4f);
    unsigned le1 = __ballot_sync(FULLM, v1 <= 1e-4f) & MB;
    int k  = __popc(le0) + __popc(le1);
    int st = min(max(k, 1), R2 - 1);
    int mi = (st + R2 - 1) >> 1;

    unsigned a0 = FULLM, a1 = MB;             // active-candidate masks (warp-uniform)
    while (true) {
        int pl = a0 ? (__ffs(a0) - 1) : (__ffs(a1) - 1);
        float pa = __shfl_sync(FULLM, v0, pl);
        float pb = __shfl_sync(FULLM, v1, pl);
        float piv = a0 ? pa : pb;
        unsigned l0 = __ballot_sync(FULLM, v0 < piv);
        unsigned l1 = __ballot_sync(FULLM, v1 < piv) & MB;
        unsigned e0 = __ballot_sync(FULLM, v0 == piv);
        unsigned e1 = __ballot_sync(FULLM, v1 == piv) & MB;
        int cl = __popc(l0) + __popc(l1);
        int ce = cl + __popc(e0) + __popc(e1);
        if (mi >= cl && mi < ce) return piv;  // value interval contains rank mi
        if (mi < cl) { a0 &= l0;          a1 &= l1; }
        else         { a0 &= ~(l0 | e0);  a1 &= ~(l1 | e1); }
    }
}

__global__ __launch_bounds__(NTHR) void fused_kernel(
    const float* __restrict__ rel,
    const float* __restrict__ depth,
    const float* __restrict__ lm,
    const float* __restrict__ sf,
    const float* __restrict__ bbox,
    float* __restrict__ out)
{
    __shared__ float  smed[LNUM];
    __shared__ float  smask[LNUM];
    __shared__ float  s_mom;
    __shared__ double redL[17], redM[17];
    __shared__ bool   s_last;

    int b    = blockIdx.x;
    int tid  = threadIdx.x;
    int wid  = tid >> 5;
    int lane = tid & 31;

    float sf0 = sf[b * 2 + 0], sf1 = sf[b * 2 + 1];
    float bx  = bbox[b * 4 + 0], by = bbox[b * 4 + 1];
    const float* dimg = depth + (size_t)b * IMG * IMG;
    const float  INF  = __int_as_float(0x7f800000);

    // ---- phase 1: region medians, 4 landmarks per warp (prefetch all loads) ----
    float v0[4], v1[4];
#pragma unroll
    for (int li = 0; li < 4; li++) {
        int l = wid * 4 + li;
        float lmx = lm[((size_t)b * LNUM + l) * 2 + 0];
        float lmy = lm[((size_t)b * LNUM + l) * 2 + 1];
        float fx = (lmx - bx) * sf0 / 224.0f * 2.0f - 1.0f;
        float fy = (lmy - by) * sf1 / 224.0f * 2.0f - 1.0f;
        v0[li] = region_val(dimg, fx, fy, lane);
        v1[li] = (lane < 17) ? region_val(dimg, fx, fy, lane + 32) : INF;
    }
#pragma unroll
    for (int li = 0; li < 4; li++) {
        float med = warp_region_median(v0[li], v1[li]);
        if (lane == 0) smed[wid * 4 + li] = med;
    }
    __syncthreads();

    // ---- phase 2: lower median-of-medians (rank 33) + mask, in-block ----
    float vraw = 0.0f;
    if (tid < LNUM) {
        vraw = smed[tid];
        int r = 0;
#pragma unroll 4
        for (int j = 0; j < LNUM; j++) {
            float w = smed[j];
            r += (w < vraw || (w == vraw && j < tid)) ? 1 : 0;  // stable rank
        }
        if (r == (LNUM - 1) / 2) s_mom = vraw;
    }
    __syncthreads();
    if (tid < LNUM) {
        smask[tid] = (fabsf(vraw - s_mom) < (90.0f / 500.0f)) ? 1.0f : 0.0f;
        smed[tid]  = vraw * 500.0f;
    }
    __syncthreads();

    // ---- phase 3: pairwise diff / mask / smooth-L1, coalesced grid-stride ----
    float* outd = out + 1;
    float* outm = out + 1 + (size_t)BS * LL;
    const size_t base = (size_t)b * LL;
    float accL = 0.0f, accM = 0.0f;
    for (int e = tid; e < LL; e += NTHR) {
        int i = e / LNUM;
        int j = e - i * LNUM;
        float diff = smed[i] - smed[j];
        float mk   = smask[i] * smask[j];
        float d    = rel[base + e] - diff;
        float ad   = fabsf(d);
        float c    = fminf(ad, 1.0f);
        float le   = c * (ad - 0.5f * c);     // == smooth-L1 (bitwise identical)
        outd[base + e] = diff;
        outm[base + e] = mk;
        accL += le * mk;
        accM += mk;
    }

    // ---- block reduce (double) + global atomics ----
    double dL = (double)accL, dM = (double)accM;
#pragma unroll
    for (int o = 16; o > 0; o >>= 1) {
        dL += __shfl_down_sync(FULLM, dL, o);
        dM += __shfl_down_sync(FULLM, dM, o);
    }
    if (lane == 0) { redL[wid] = dL; redM[wid] = dM; }
    __syncthreads();
    if (tid == 0) {
        double tL = 0.0, tM = 0.0;
#pragma unroll
        for (int w = 0; w < 17; w++) { tL += redL[w]; tM += redM[w]; }
        atomicAdd(&g_sumL, tL);
        atomicAdd(&g_sumM, tM);
        __threadfence();
        unsigned n = atomicAdd(&g_done, 1u);
        s_last = (n == BS - 1);
    }
    __syncthreads();

    // ---- last block finalizes scalar loss and resets state for next replay ----
    if (s_last && tid == 0) {
        __threadfence();
        double L = g_sumL, M = g_sumM;
        out[0] = (float)(L / (M + 1e-4));
        g_sumL = 0.0; g_sumM = 0.0; g_done = 0u;
    }
}

extern "C" void kernel_launch(void* const* d_in, const int* in_sizes, int n_in,
                              void* d_out, int out_size)
{
    const float* rel   = (const float*)d_in[0];   // [BS, L, L]
    const float* depth = (const float*)d_in[1];   // [BS, 1, IMG, IMG]
    const float* lm    = (const float*)d_in[2];   // [BS, L, 2]
    const float* sf    = (const float*)d_in[3];   // [BS, 2]
    const float* bbox  = (const float*)d_in[4];   // [BS, 4]
    float* out = (float*)d_out;                   // [loss | diff | mask]

    fused_kernel<<<BS, NTHR>>>(rel, depth, lm, sf, bbox, out);
}